// round 12
// baseline (speedup 1.0000x reference)
#include <cuda_runtime.h>
#include <cuda_fp16.h>
#include <cuda_bf16.h>

// Problem constants
#define MAXN 100000
#define MAXE 1600000

typedef unsigned long long ull;
typedef unsigned int u32;

// ---------------- scratch (device globals — no runtime allocation) ----------
__device__ int    g_is64;            // 1 if ei_feat is int64, 0 if int32
__device__ int    g_cnt[MAXN];
__device__ float  g_dinv[MAXN];
__device__ int    g_off[MAXN + 1];
__device__ int    g_rank[MAXE];      // per-edge rank within its dst bucket
__device__ int    g_csr[MAXE];
__device__ int    g_bsum[256];       // decoupled scan: block_sum+1 (0 = not ready)
__device__ __half g_Xh[MAXN * 64];   // fp16(dinv[n] * X[n])        (gather src 1)
__device__ __half g_Fph[MAXN * 64];  // fp16(dinv[n] * (H @ Wf)[n]) (gather src 2)
// pre-transposed fp16 weights, padded rows for conflict-free ldmatrix
__device__ __half g_WTa[256 * 40];   // [n(256)][k(32)+8pad]  (Wn rows 0-127, Ws 128-255)
__device__ __half g_WfT[64 * 264];   // [n(64)][k(256)+8pad]

// ---------------- helpers ---------------------------------------------------
__device__ __forceinline__ int clampN(int v, int N) {
    v = v < 0 ? 0 : v;
    return v >= N ? N - 1 : v;
}

__device__ __forceinline__ int edge_at(const void* ei, int idx) {
    return g_is64 ? ((const int*)ei)[2 * idx] : ((const int*)ei)[idx];
}

__device__ __forceinline__ float elu1(float v) {
    return v > 0.f ? v : (__expf(v) - 1.0f);
}

__device__ __forceinline__ void hadd4u(float4& a, u32 lo, u32 hi) {
    float2 f0 = __half22float2(*reinterpret_cast<__half2*>(&lo));
    float2 f1 = __half22float2(*reinterpret_cast<__half2*>(&hi));
    a.x += f0.x; a.y += f0.y; a.z += f1.x; a.w += f1.y;
}

__device__ __forceinline__ uint2 pack4h(float a, float b, float c, float d) {
    union { __half2 h[2]; uint2 u; } cv;
    cv.h[0] = __floats2half2_rn(a, b);
    cv.h[1] = __floats2half2_rn(c, d);
    return cv.u;
}

__device__ __forceinline__ u32 s2u(const void* p) {
    return (u32)__cvta_generic_to_shared(p);
}
__device__ __forceinline__ void ldsm4(u32* r, u32 a) {
    asm volatile("ldmatrix.sync.aligned.m8n8.x4.shared.b16 {%0,%1,%2,%3}, [%4];"
        : "=r"(r[0]), "=r"(r[1]), "=r"(r[2]), "=r"(r[3]) : "r"(a));
}
__device__ __forceinline__ void ldsm2(u32* r, u32 a) {
    asm volatile("ldmatrix.sync.aligned.m8n8.x2.shared.b16 {%0,%1}, [%2];"
        : "=r"(r[0]), "=r"(r[1]) : "r"(a));
}
__device__ __forceinline__ void mma16816(float* c, const u32* a, const u32* b) {
    asm volatile("mma.sync.aligned.m16n8k16.row.col.f32.f16.f16.f32 "
        "{%0,%1,%2,%3}, {%4,%5,%6,%7}, {%8,%9}, {%0,%1,%2,%3};"
        : "+f"(c[0]), "+f"(c[1]), "+f"(c[2]), "+f"(c[3])
        : "r"(a[0]), "r"(a[1]), "r"(a[2]), "r"(a[3]), "r"(b[0]), "r"(b[1]));
}

// ---------------- k_init: dtype detect + zero cnt/bsum + weight fp16 --------
__global__ void k_init(const unsigned int* __restrict__ w, int E, int N,
                       const float* __restrict__ Wn, const float* __restrict__ Ws,
                       const float* __restrict__ Wf) {
    if (blockIdx.x == 0) {
        if (threadIdx.x == 0) g_is64 = 1;
        __syncthreads();
        int npairs = E < 1024 ? E : 1024;
        if ((int)threadIdx.x < npairs) {
            if (w[2 * threadIdx.x + 1] != 0u) atomicExch(&g_is64, 0);
        }
    }
    if (blockIdx.x == 1 && threadIdx.x < 256) g_bsum[threadIdx.x] = 0;

    int stride = gridDim.x * blockDim.x;
    int gtid = blockIdx.x * blockDim.x + threadIdx.x;
    for (int i = gtid; i < N; i += stride) g_cnt[i] = 0;
    for (int idx = gtid; idx < 4096; idx += stride) {
        int k = idx >> 7, n = idx & 127;           // Wn/Ws are [32][128]
        g_WTa[n * 40 + k]         = __float2half_rn(Wn[idx]);
        g_WTa[(n + 128) * 40 + k] = __float2half_rn(Ws[idx]);
    }
    for (int idx = gtid; idx < 16384; idx += stride) {
        int k = idx >> 6, n = idx & 63;            // Wf is [256][64]
        g_WfT[n * 264 + k] = __float2half_rn(Wf[idx]);
    }
}

// ---------------- CSR build -------------------------------------------------
// hist also records each edge's rank within its dst bucket (the old counter
// value the atomic returns) so k_fill needs no atomics at all.
__global__ void k_hist(const void* __restrict__ ei, int E, int N) {
    int e = blockIdx.x * blockDim.x + threadIdx.x;
    if (e < E) {
        int dst = clampN(edge_at(ei, E + e), N);
        g_rank[e] = atomicAdd(&g_cnt[dst], 1);
    }
}

// Single-kernel scan (decoupled aggregate lookback) + fp16 feature prep fused.
// All <=98 blocks are co-resident on 148 SMs (wave 1), so polling is safe.
__global__ void k_scan(int N, int E, const float* __restrict__ X) {
    __shared__ int wsum[32];
    __shared__ int sPrefix;
    int tid = threadIdx.x, bid = blockIdx.x;
    int lane = tid & 31, wid = tid >> 5;
    int i = bid * 1024 + tid;
    int v = (i < N) ? g_cnt[i] : 0;

    // block-wide inclusive scan (shuffle)
    int incl = v;
#pragma unroll
    for (int o = 1; o < 32; o <<= 1) {
        int t = __shfl_up_sync(0xffffffffu, incl, o);
        if (lane >= o) incl += t;
    }
    if (lane == 31) wsum[wid] = incl;
    __syncthreads();
    if (wid == 0) {
        int wv = wsum[lane];
#pragma unroll
        for (int o = 1; o < 32; o <<= 1) {
            int t = __shfl_up_sync(0xffffffffu, wv, o);
            if (lane >= o) wv += t;
        }
        wsum[lane] = wv;                       // inclusive warp sums
    }
    __syncthreads();
    int incl_total = incl + (wid ? wsum[wid - 1] : 0);
    int block_sum = wsum[31];

    // publish our aggregate (value+1 so 0 == not-ready; single word => atomic)
    if (tid == 0) {
        atomicExch(&g_bsum[bid], block_sum + 1);
        sPrefix = 0;
    }
    __syncthreads();

    // lookback: poll all predecessors in parallel
    for (int b = tid; b < bid; b += 1024) {
        int vb;
        do { vb = atomicAdd(&g_bsum[b], 0); } while (vb == 0);
        atomicAdd_block(&sPrefix, vb - 1);
    }
    __syncthreads();
    int prefix = sPrefix;

    if (i < N) {
        int excl = prefix + incl_total - v;
        g_off[i] = excl;
        float dn = rsqrtf((float)(v + 1));
        g_dinv[i] = dn;
        // fused prep: g_Xh[i] = fp16(dinv * X[i])
        const float4* xp = (const float4*)(X + (size_t)i * 64);
        uint2* dp = (uint2*)(g_Xh + (size_t)i * 64);
#pragma unroll
        for (int q = 0; q < 16; ++q) {
            float4 f = xp[q];
            dp[q] = pack4h(f.x * dn, f.y * dn, f.z * dn, f.w * dn);
        }
    }
    if (bid == 0 && tid == 0) g_off[N] = E;
}

// atomic-free fill: pos = off[dst] + rank[e]
__global__ void k_fill(const void* __restrict__ ei, int E, int N) {
    int e = blockIdx.x * blockDim.x + threadIdx.x;
    if (e < E) {
        int dst = clampN(edge_at(ei, E + e), N);
        int src = clampN(edge_at(ei, e), N);
        int pos = g_off[dst] + g_rank[e];
        if (pos < MAXE) g_csr[pos] = src;
    }
}

// ---------------- fused agg + HMMA MLP --------------------------------------
// Layouts (halves): sXh [64][72], sWTa [256][40], sH [64][264], sWfT [64][264]
#define OFF_XH   0
#define OFF_WTA  4608
#define OFF_H    14848
#define OFF_WFT  31744
#define HALVES_TOTAL 48640
#define MLP_SMEM_BYTES (HALVES_TOTAL * 2 + 256 * 4 + 64 * 4)

__global__ __launch_bounds__(256)
void k_aggmlp(const float* __restrict__ bn, const float* __restrict__ bs, int N) {
    extern __shared__ __half smh[];
    float* sBias = (float*)(smh + HALVES_TOTAL);
    float* sDinv = sBias + 256;

    int tid = threadIdx.x;
    int node0 = blockIdx.x * 64;
    int w = tid >> 5, lane = tid & 31;

    // ---- stage weights + bias + dinv ----
    {
        const uint4* s1 = (const uint4*)g_WTa;
        uint4* d1 = (uint4*)(smh + OFF_WTA);
        for (int i = tid; i < 1280; i += 256) d1[i] = s1[i];
        const uint4* s2 = (const uint4*)g_WfT;
        uint4* d2 = (uint4*)(smh + OFF_WFT);
        for (int i = tid; i < 2112; i += 256) d2[i] = s2[i];
        sBias[tid] = (tid < 128) ? bn[tid] : bs[tid - 128];
        if (tid < 64) {
            int n = node0 + tid;
            sDinv[tid] = (n < N) ? g_dinv[n] : 0.f;
        }
    }

    // ---- Phase 0: gather-aggregate (uint4, 8 lanes/node) into sXh fp16 ----
    {
        int glane = tid & 7;             // 8 lanes per node, 8 halves each
        int nsub = tid >> 3;             // 32 nodes per pass, 2 passes
        const uint4* feat = (const uint4*)g_Xh;   // row = 8 uint4
#pragma unroll
        for (int pass = 0; pass < 2; ++pass) {
            int row = pass * 32 + nsub;
            int n = node0 + row;
            float4 a0 = {0.f, 0.f, 0.f, 0.f};
            float4 a1 = {0.f, 0.f, 0.f, 0.f};
            if (n < N) {
                uint4 sv = feat[n * 8 + glane];    // self-loop term
                hadd4u(a0, sv.x, sv.y); hadd4u(a1, sv.z, sv.w);
                int beg = g_off[n], end = g_off[n + 1];
                int j = beg;
                for (; j + 4 <= end; j += 4) {
                    int u[4];
#pragma unroll
                    for (int t = 0; t < 4; ++t) u[t] = g_csr[j + t];
                    uint4 v4[4];
#pragma unroll
                    for (int t = 0; t < 4; ++t) v4[t] = feat[u[t] * 8 + glane];
#pragma unroll
                    for (int t = 0; t < 4; ++t) {
                        hadd4u(a0, v4[t].x, v4[t].y);
                        hadd4u(a1, v4[t].z, v4[t].w);
                    }
                }
                for (; j < end; ++j) {
                    uint4 vv = feat[g_csr[j] * 8 + glane];
                    hadd4u(a0, vv.x, vv.y); hadd4u(a1, vv.z, vv.w);
                }
                float dn = g_dinv[n];
                a0.x *= dn; a0.y *= dn; a0.z *= dn; a0.w *= dn;
                a1.x *= dn; a1.y *= dn; a1.z *= dn; a1.w *= dn;
            }
            uint2 p0 = pack4h(a0.x, a0.y, a0.z, a0.w);
            uint2 p1 = pack4h(a1.x, a1.y, a1.z, a1.w);
            *(uint4*)&smh[OFF_XH + row * 72 + glane * 8] =
                make_uint4(p0.x, p0.y, p1.x, p1.y);
        }
    }
    __syncthreads();

    // ---- Phase A: H[64][256] = elu(Xt @ blockdiag(Wn,Ws) + b), warp = 32 cols
    {
        int hsel = w >> 2;              // warps 0-3: cols 0-127 (nuc), 4-7: surf
        int n0w = w * 32;               // global col base
        float c[4][4][4];
#pragma unroll
        for (int mt = 0; mt < 4; ++mt)
#pragma unroll
            for (int nt = 0; nt < 4; ++nt)
#pragma unroll
                for (int i = 0; i < 4; ++i) c[mt][nt][i] = 0.f;

        u32 bfr[4][2][2];
#pragma unroll
        for (int nt = 0; nt < 4; ++nt)
#pragma unroll
            for (int ks = 0; ks < 2; ++ks) {
                int row = n0w + nt * 8 + (lane & 7);
                int col = ks * 16 + ((lane >> 3) & 1) * 8;
                ldsm2(bfr[nt][ks], s2u(&smh[OFF_WTA + row * 40 + col]));
            }

#pragma unroll
        for (int mt = 0; mt < 4; ++mt) {
            u32 afr[2][4];
#pragma unroll
            for (int ks = 0; ks < 2; ++ks) {
                int row = mt * 16 + (lane & 15);
                int col = hsel * 32 + ks * 16 + (lane >> 4) * 8;
                ldsm4(afr[ks], s2u(&smh[OFF_XH + row * 72 + col]));
            }
#pragma unroll
            for (int nt = 0; nt < 4; ++nt) {
                mma16816(c[mt][nt], afr[0], bfr[nt][0]);
                mma16816(c[mt][nt], afr[1], bfr[nt][1]);
            }
        }

        // epilogue: bias + elu -> sH fp16
#pragma unroll
        for (int mt = 0; mt < 4; ++mt)
#pragma unroll
            for (int nt = 0; nt < 4; ++nt) {
                int colg = n0w + nt * 8 + 2 * (lane & 3);
                float b0 = sBias[colg], b1 = sBias[colg + 1];
                int r0 = mt * 16 + (lane >> 2);
                *(__half2*)&smh[OFF_H + r0 * 264 + colg] =
                    __floats2half2_rn(elu1(c[mt][nt][0] + b0), elu1(c[mt][nt][1] + b1));
                *(__half2*)&smh[OFF_H + (r0 + 8) * 264 + colg] =
                    __floats2half2_rn(elu1(c[mt][nt][2] + b0), elu1(c[mt][nt][3] + b1));
            }
    }
    __syncthreads();

    // ---- Phase B: Fp[64][64] = dinv * (H @ Wf), warp tile 16x32, K=256 ----
    {
        int m0 = (w & 3) * 16, n0b = (w >> 2) * 32;
        float c2[4][4];
#pragma unroll
        for (int nt = 0; nt < 4; ++nt)
#pragma unroll
            for (int i = 0; i < 4; ++i) c2[nt][i] = 0.f;

        for (int ks = 0; ks < 16; ++ks) {
            int k0 = ks * 16;
            u32 afr[4];
            {
                int row = m0 + (lane & 15);
                int col = k0 + (lane >> 4) * 8;
                ldsm4(afr, s2u(&smh[OFF_H + row * 264 + col]));
            }
#pragma unroll
            for (int nt = 0; nt < 4; ++nt) {
                u32 bfr[2];
                int row = n0b + nt * 8 + (lane & 7);
                int col = k0 + ((lane >> 3) & 1) * 8;
                ldsm2(bfr, s2u(&smh[OFF_WFT + row * 264 + col]));
                mma16816(c2[nt], afr, bfr);
            }
        }

#pragma unroll
        for (int nt = 0; nt < 4; ++nt) {
            int colg = n0b + nt * 8 + 2 * (lane & 3);
            int r0 = m0 + (lane >> 2), r1 = r0 + 8;
            int ng0 = node0 + r0, ng1 = node0 + r1;
            if (ng0 < N) {
                float d = sDinv[r0];
                *(__half2*)&g_Fph[ng0 * 64 + colg] =
                    __floats2half2_rn(c2[nt][0] * d, c2[nt][1] * d);
            }
            if (ng1 < N) {
                float d = sDinv[r1];
                *(__half2*)&g_Fph[ng1 * 64 + colg] =
                    __floats2half2_rn(c2[nt][2] * d, c2[nt][3] * d);
            }
        }
    }
}

// ---------------- layer-2 aggregation + bias + softmax (uint4 gather) -------
__global__ void k_agg_softmax(const float* __restrict__ bf, float* __restrict__ out, int N) {
    int tid = threadIdx.x;
    int glane = tid & 7;                 // 8 lanes per node, 8 logits each
    int n = blockIdx.x * 32 + (tid >> 3);
    if (n >= N) return;
    const uint4* feat = (const uint4*)g_Fph;
    float4 a0 = {0.f, 0.f, 0.f, 0.f};
    float4 a1 = {0.f, 0.f, 0.f, 0.f};
    {
        uint4 sv = feat[n * 8 + glane];  // self-loop term
        hadd4u(a0, sv.x, sv.y); hadd4u(a1, sv.z, sv.w);
    }
    int beg = g_off[n], end = g_off[n + 1];
    int j = beg;
    for (; j + 4 <= end; j += 4) {
        int u[4];
#pragma unroll
        for (int t = 0; t < 4; ++t) u[t] = g_csr[j + t];
        uint4 v4[4];
#pragma unroll
        for (int t = 0; t < 4; ++t) v4[t] = feat[u[t] * 8 + glane];
#pragma unroll
        for (int t = 0; t < 4; ++t) {
            hadd4u(a0, v4[t].x, v4[t].y);
            hadd4u(a1, v4[t].z, v4[t].w);
        }
    }
    for (; j < end; ++j) {
        uint4 vv = feat[g_csr[j] * 8 + glane];
        hadd4u(a0, vv.x, vv.y); hadd4u(a1, vv.z, vv.w);
    }
    float s = g_dinv[n];
    float4 b0 = ((const float4*)bf)[glane * 2];
    float4 b1 = ((const float4*)bf)[glane * 2 + 1];
    float4 z0 = {a0.x * s + b0.x, a0.y * s + b0.y, a0.z * s + b0.z, a0.w * s + b0.w};
    float4 z1 = {a1.x * s + b1.x, a1.y * s + b1.y, a1.z * s + b1.z, a1.w * s + b1.w};

    // softmax over 64 logits spread across 8 lanes (8 each)
    float m = fmaxf(fmaxf(fmaxf(z0.x, z0.y), fmaxf(z0.z, z0.w)),
                    fmaxf(fmaxf(z1.x, z1.y), fmaxf(z1.z, z1.w)));
#pragma unroll
    for (int o = 4; o > 0; o >>= 1)
        m = fmaxf(m, __shfl_xor_sync(0xffffffffu, m, o, 8));
    z0.x = __expf(z0.x - m); z0.y = __expf(z0.y - m);
    z0.z = __expf(z0.z - m); z0.w = __expf(z0.w - m);
    z1.x = __expf(z1.x - m); z1.y = __expf(z1.y - m);
    z1.z = __expf(z1.z - m); z1.w = __expf(z1.w - m);
    float sum = z0.x + z0.y + z0.z + z0.w + z1.x + z1.y + z1.z + z1.w;
#pragma unroll
    for (int o = 4; o > 0; o >>= 1)
        sum += __shfl_xor_sync(0xffffffffu, sum, o, 8);
    float inv = 1.0f / sum;
    z0.x *= inv; z0.y *= inv; z0.z *= inv; z0.w *= inv;
    z1.x *= inv; z1.y *= inv; z1.z *= inv; z1.w *= inv;
    ((float4*)out)[n * 16 + glane * 2]     = z0;
    ((float4*)out)[n * 16 + glane * 2 + 1] = z1;
}

// ---------------- launch ----------------------------------------------------
extern "C" void kernel_launch(void* const* d_in, const int* in_sizes, int n_in,
                              void* d_out, int out_size) {
    const float* X  = (const float*)d_in[0];
    const void*  ei = d_in[1];            // int32 or int64 — detected on device
    const float* Wn = (const float*)d_in[3];
    const float* bn = (const float*)d_in[4];
    const float* Ws = (const float*)d_in[5];
    const float* bs = (const float*)d_in[6];
    const float* Wf = (const float*)d_in[7];
    const float* bf = (const float*)d_in[8];
    float* out = (float*)d_out;

    int N = in_sizes[0] / 64;
    int E = in_sizes[1] / 2;
    int NB = (N + 1023) / 1024;
    int NB64 = (N + 63) / 64;

    cudaFuncSetAttribute(k_aggmlp, cudaFuncAttributeMaxDynamicSharedMemorySize,
                         MLP_SMEM_BYTES);

    k_init<<<128, 1024>>>((const unsigned int*)ei, E, N, Wn, Ws, Wf);
    k_hist<<<(E + 511) / 512, 512>>>(ei, E, N);
    k_scan<<<NB, 1024>>>(N, E, X);
    k_fill<<<(E + 511) / 512, 512>>>(ei, E, N);
    k_aggmlp<<<NB64, 256, MLP_SMEM_BYTES>>>(bn, bs, N);
    k_agg_softmax<<<(N + 31) / 32, 256>>>(bf, out, N);
}

// round 13
// speedup vs baseline: 1.0737x; 1.0737x over previous
#include <cuda_runtime.h>
#include <cuda_fp16.h>
#include <cuda_bf16.h>

// Problem constants
#define MAXN 100000
#define MAXE 1600000

typedef unsigned long long ull;
typedef unsigned int u32;

// ---------------- scratch (device globals — no runtime allocation) ----------
__device__ int    g_is64;            // 1 if ei_feat is int64, 0 if int32
__device__ int    g_cnt[MAXN];
__device__ float  g_dinv[MAXN];
__device__ int    g_off[MAXN + 1];
__device__ int    g_cur[MAXN];
__device__ int    g_csr[MAXE];
__device__ int    g_bsum[256];       // decoupled scan: block_sum+1 (0 = not ready)
__device__ __half g_Xh[MAXN * 64];   // fp16(dinv[n] * X[n])        (gather src 1)
__device__ __half g_Fph[MAXN * 64];  // fp16(dinv[n] * (H @ Wf)[n]) (gather src 2)
// pre-transposed fp16 weights, padded rows for conflict-free ldmatrix
__device__ __half g_WTa[256 * 40];   // [n(256)][k(32)+8pad]  (Wn rows 0-127, Ws 128-255)
__device__ __half g_WfT[64 * 264];   // [n(64)][k(256)+8pad]

// ---------------- helpers ---------------------------------------------------
__device__ __forceinline__ int clampN(int v, int N) {
    v = v < 0 ? 0 : v;
    return v >= N ? N - 1 : v;
}

__device__ __forceinline__ int edge_at(const void* ei, int idx) {
    return g_is64 ? ((const int*)ei)[2 * idx] : ((const int*)ei)[idx];
}

__device__ __forceinline__ float elu1(float v) {
    return v > 0.f ? v : (__expf(v) - 1.0f);
}

__device__ __forceinline__ void hadd4u(float4& a, u32 lo, u32 hi) {
    float2 f0 = __half22float2(*reinterpret_cast<__half2*>(&lo));
    float2 f1 = __half22float2(*reinterpret_cast<__half2*>(&hi));
    a.x += f0.x; a.y += f0.y; a.z += f1.x; a.w += f1.y;
}

__device__ __forceinline__ uint2 pack4h(float a, float b, float c, float d) {
    union { __half2 h[2]; uint2 u; } cv;
    cv.h[0] = __floats2half2_rn(a, b);
    cv.h[1] = __floats2half2_rn(c, d);
    return cv.u;
}

__device__ __forceinline__ u32 s2u(const void* p) {
    return (u32)__cvta_generic_to_shared(p);
}
__device__ __forceinline__ void ldsm4(u32* r, u32 a) {
    asm volatile("ldmatrix.sync.aligned.m8n8.x4.shared.b16 {%0,%1,%2,%3}, [%4];"
        : "=r"(r[0]), "=r"(r[1]), "=r"(r[2]), "=r"(r[3]) : "r"(a));
}
__device__ __forceinline__ void ldsm2(u32* r, u32 a) {
    asm volatile("ldmatrix.sync.aligned.m8n8.x2.shared.b16 {%0,%1}, [%2];"
        : "=r"(r[0]), "=r"(r[1]) : "r"(a));
}
__device__ __forceinline__ void mma16816(float* c, const u32* a, const u32* b) {
    asm volatile("mma.sync.aligned.m16n8k16.row.col.f32.f16.f16.f32 "
        "{%0,%1,%2,%3}, {%4,%5,%6,%7}, {%8,%9}, {%0,%1,%2,%3};"
        : "+f"(c[0]), "+f"(c[1]), "+f"(c[2]), "+f"(c[3])
        : "r"(a[0]), "r"(a[1]), "r"(a[2]), "r"(a[3]), "r"(b[0]), "r"(b[1]));
}

// ---------------- k_init: dtype detect + zero cnt/bsum + weight fp16 --------
__global__ void k_init(const unsigned int* __restrict__ w, int E, int N,
                       const float* __restrict__ Wn, const float* __restrict__ Ws,
                       const float* __restrict__ Wf) {
    if (blockIdx.x == 0) {
        if (threadIdx.x == 0) g_is64 = 1;
        __syncthreads();
        int npairs = E < 1024 ? E : 1024;
        if ((int)threadIdx.x < npairs) {
            if (w[2 * threadIdx.x + 1] != 0u) atomicExch(&g_is64, 0);
        }
    }
    if (blockIdx.x == 1 && threadIdx.x < 256) g_bsum[threadIdx.x] = 0;

    int stride = gridDim.x * blockDim.x;
    int gtid = blockIdx.x * blockDim.x + threadIdx.x;
    for (int i = gtid; i < N; i += stride) g_cnt[i] = 0;
    for (int idx = gtid; idx < 4096; idx += stride) {
        int k = idx >> 7, n = idx & 127;           // Wn/Ws are [32][128]
        g_WTa[n * 40 + k]         = __float2half_rn(Wn[idx]);
        g_WTa[(n + 128) * 40 + k] = __float2half_rn(Ws[idx]);
    }
    for (int idx = gtid; idx < 16384; idx += stride) {
        int k = idx >> 6, n = idx & 63;            // Wf is [256][64]
        g_WfT[n * 264 + k] = __float2half_rn(Wf[idx]);
    }
}

// ---------------- CSR build -------------------------------------------------
// hist discards the atomic result -> ptxas emits REDG (fire-and-forget).
__global__ void k_hist(const void* __restrict__ ei, int E, int N) {
    int e = blockIdx.x * blockDim.x + threadIdx.x;
    if (e < E) {
        int dst = clampN(edge_at(ei, E + e), N);
        atomicAdd(&g_cnt[dst], 1);
    }
}

// Single-kernel scan: warp-shuffle block scan + decoupled aggregate lookback.
// All <=98 blocks are co-resident on 148 SMs (wave 1), so polling is safe.
__global__ void k_scan(int N, int E) {
    __shared__ int wsum[32];
    __shared__ int sPrefix;
    int tid = threadIdx.x, bid = blockIdx.x;
    int lane = tid & 31, wid = tid >> 5;
    int i = bid * 1024 + tid;
    int v = (i < N) ? g_cnt[i] : 0;

    // block-wide inclusive scan (shuffle)
    int incl = v;
#pragma unroll
    for (int o = 1; o < 32; o <<= 1) {
        int t = __shfl_up_sync(0xffffffffu, incl, o);
        if (lane >= o) incl += t;
    }
    if (lane == 31) wsum[wid] = incl;
    __syncthreads();
    if (wid == 0) {
        int wv = wsum[lane];
#pragma unroll
        for (int o = 1; o < 32; o <<= 1) {
            int t = __shfl_up_sync(0xffffffffu, wv, o);
            if (lane >= o) wv += t;
        }
        wsum[lane] = wv;                       // inclusive warp sums
    }
    __syncthreads();
    int incl_total = incl + (wid ? wsum[wid - 1] : 0);
    int block_sum = wsum[31];

    // publish our aggregate (value+1 so 0 == not-ready; single word => atomic)
    if (tid == 0) {
        atomicExch(&g_bsum[bid], block_sum + 1);
        sPrefix = 0;
    }
    __syncthreads();

    // lookback: poll all predecessors in parallel
    for (int b = tid; b < bid; b += 1024) {
        int vb;
        do { vb = atomicAdd(&g_bsum[b], 0); } while (vb == 0);
        atomicAdd_block(&sPrefix, vb - 1);
    }
    __syncthreads();
    int prefix = sPrefix;

    if (i < N) {
        int excl = prefix + incl_total - v;
        g_off[i] = excl;
        g_cur[i] = excl;
        g_dinv[i] = rsqrtf((float)(v + 1));
    }
    if (bid == 0 && tid == 0) g_off[N] = E;
}

// ---------------- fused fill + prep (block-specialized) ----------------------
// Blocks [0, FB): CSR fill, 4 edges/thread (4 independent atomics in flight).
// Blocks [FB, grid): g_Xh = fp16(dinv * X), pure-bandwidth work that hides in
// the fill blocks' atomic-stall issue slots. Both depend only on k_scan.
__global__ void k_fillprep(const void* __restrict__ ei, int E, int N,
                           const float* __restrict__ X, int FB) {
    if ((int)blockIdx.x < FB) {
        int e0 = blockIdx.x * 2048 + threadIdx.x;
        int dst[4], src[4];
        bool valid[4];
#pragma unroll
        for (int k = 0; k < 4; ++k) {
            int e = e0 + k * 512;
            valid[k] = e < E;
            if (valid[k]) {
                dst[k] = clampN(edge_at(ei, E + e), N);
                src[k] = clampN(edge_at(ei, e), N);
            }
        }
        int pos[4];
#pragma unroll
        for (int k = 0; k < 4; ++k)
            if (valid[k]) pos[k] = atomicAdd(&g_cur[dst[k]], 1);
#pragma unroll
        for (int k = 0; k < 4; ++k)
            if (valid[k] && pos[k] < MAXE) g_csr[pos[k]] = src[k];
    } else {
        int total = N * 16;                      // float4 quads
        int nthr = (gridDim.x - FB) * 512;
        for (int idx = (blockIdx.x - FB) * 512 + threadIdx.x; idx < total; idx += nthr) {
            int n = idx >> 4;
            float s = g_dinv[n];
            float4 v = ((const float4*)X)[idx];
            ((uint2*)g_Xh)[idx] = pack4h(v.x * s, v.y * s, v.z * s, v.w * s);
        }
    }
}

// ---------------- fused agg + HMMA MLP --------------------------------------
// Layouts (halves): sXh [64][72], sWTa [256][40], sH [64][264], sWfT [64][264]
#define OFF_XH   0
#define OFF_WTA  4608
#define OFF_H    14848
#define OFF_WFT  31744
#define HALVES_TOTAL 48640
#define MLP_SMEM_BYTES (HALVES_TOTAL * 2 + 256 * 4 + 64 * 4)

__global__ __launch_bounds__(256)
void k_aggmlp(const float* __restrict__ bn, const float* __restrict__ bs, int N) {
    extern __shared__ __half smh[];
    float* sBias = (float*)(smh + HALVES_TOTAL);
    float* sDinv = sBias + 256;

    int tid = threadIdx.x;
    int node0 = blockIdx.x * 64;
    int w = tid >> 5, lane = tid & 31;

    // ---- stage weights + bias + dinv ----
    {
        const uint4* s1 = (const uint4*)g_WTa;
        uint4* d1 = (uint4*)(smh + OFF_WTA);
        for (int i = tid; i < 1280; i += 256) d1[i] = s1[i];
        const uint4* s2 = (const uint4*)g_WfT;
        uint4* d2 = (uint4*)(smh + OFF_WFT);
        for (int i = tid; i < 2112; i += 256) d2[i] = s2[i];
        sBias[tid] = (tid < 128) ? bn[tid] : bs[tid - 128];
        if (tid < 64) {
            int n = node0 + tid;
            sDinv[tid] = (n < N) ? g_dinv[n] : 0.f;
        }
    }

    // ---- Phase 0: gather-aggregate (uint4, 8 lanes/node) into sXh fp16 ----
    {
        int glane = tid & 7;             // 8 lanes per node, 8 halves each
        int nsub = tid >> 3;             // 32 nodes per pass, 2 passes
        const uint4* feat = (const uint4*)g_Xh;   // row = 8 uint4
#pragma unroll
        for (int pass = 0; pass < 2; ++pass) {
            int row = pass * 32 + nsub;
            int n = node0 + row;
            float4 a0 = {0.f, 0.f, 0.f, 0.f};
            float4 a1 = {0.f, 0.f, 0.f, 0.f};
            if (n < N) {
                uint4 sv = feat[n * 8 + glane];    // self-loop term
                hadd4u(a0, sv.x, sv.y); hadd4u(a1, sv.z, sv.w);
                int beg = g_off[n], end = g_off[n + 1];
                int j = beg;
                for (; j + 4 <= end; j += 4) {
                    int u[4];
#pragma unroll
                    for (int t = 0; t < 4; ++t) u[t] = g_csr[j + t];
                    uint4 v4[4];
#pragma unroll
                    for (int t = 0; t < 4; ++t) v4[t] = feat[u[t] * 8 + glane];
#pragma unroll
                    for (int t = 0; t < 4; ++t) {
                        hadd4u(a0, v4[t].x, v4[t].y);
                        hadd4u(a1, v4[t].z, v4[t].w);
                    }
                }
                for (; j < end; ++j) {
                    uint4 vv = feat[g_csr[j] * 8 + glane];
                    hadd4u(a0, vv.x, vv.y); hadd4u(a1, vv.z, vv.w);
                }
                float dn = g_dinv[n];
                a0.x *= dn; a0.y *= dn; a0.z *= dn; a0.w *= dn;
                a1.x *= dn; a1.y *= dn; a1.z *= dn; a1.w *= dn;
            }
            uint2 p0 = pack4h(a0.x, a0.y, a0.z, a0.w);
            uint2 p1 = pack4h(a1.x, a1.y, a1.z, a1.w);
            *(uint4*)&smh[OFF_XH + row * 72 + glane * 8] =
                make_uint4(p0.x, p0.y, p1.x, p1.y);
        }
    }
    __syncthreads();

    // ---- Phase A: H[64][256] = elu(Xt @ blockdiag(Wn,Ws) + b), warp = 32 cols
    {
        int hsel = w >> 2;              // warps 0-3: cols 0-127 (nuc), 4-7: surf
        int n0w = w * 32;               // global col base
        float c[4][4][4];
#pragma unroll
        for (int mt = 0; mt < 4; ++mt)
#pragma unroll
            for (int nt = 0; nt < 4; ++nt)
#pragma unroll
                for (int i = 0; i < 4; ++i) c[mt][nt][i] = 0.f;

        u32 bfr[4][2][2];
#pragma unroll
        for (int nt = 0; nt < 4; ++nt)
#pragma unroll
            for (int ks = 0; ks < 2; ++ks) {
                int row = n0w + nt * 8 + (lane & 7);
                int col = ks * 16 + ((lane >> 3) & 1) * 8;
                ldsm2(bfr[nt][ks], s2u(&smh[OFF_WTA + row * 40 + col]));
            }

#pragma unroll
        for (int mt = 0; mt < 4; ++mt) {
            u32 afr[2][4];
#pragma unroll
            for (int ks = 0; ks < 2; ++ks) {
                int row = mt * 16 + (lane & 15);
                int col = hsel * 32 + ks * 16 + (lane >> 4) * 8;
                ldsm4(afr[ks], s2u(&smh[OFF_XH + row * 72 + col]));
            }
#pragma unroll
            for (int nt = 0; nt < 4; ++nt) {
                mma16816(c[mt][nt], afr[0], bfr[nt][0]);
                mma16816(c[mt][nt], afr[1], bfr[nt][1]);
            }
        }

        // epilogue: bias + elu -> sH fp16
#pragma unroll
        for (int mt = 0; mt < 4; ++mt)
#pragma unroll
            for (int nt = 0; nt < 4; ++nt) {
                int colg = n0w + nt * 8 + 2 * (lane & 3);
                float b0 = sBias[colg], b1 = sBias[colg + 1];
                int r0 = mt * 16 + (lane >> 2);
                *(__half2*)&smh[OFF_H + r0 * 264 + colg] =
                    __floats2half2_rn(elu1(c[mt][nt][0] + b0), elu1(c[mt][nt][1] + b1));
                *(__half2*)&smh[OFF_H + (r0 + 8) * 264 + colg] =
                    __floats2half2_rn(elu1(c[mt][nt][2] + b0), elu1(c[mt][nt][3] + b1));
            }
    }
    __syncthreads();

    // ---- Phase B: Fp[64][64] = dinv * (H @ Wf), warp tile 16x32, K=256 ----
    {
        int m0 = (w & 3) * 16, n0b = (w >> 2) * 32;
        float c2[4][4];
#pragma unroll
        for (int nt = 0; nt < 4; ++nt)
#pragma unroll
            for (int i = 0; i < 4; ++i) c2[nt][i] = 0.f;

        for (int ks = 0; ks < 16; ++ks) {
            int k0 = ks * 16;
            u32 afr[4];
            {
                int row = m0 + (lane & 15);
                int col = k0 + (lane >> 4) * 8;
                ldsm4(afr, s2u(&smh[OFF_H + row * 264 + col]));
            }
#pragma unroll
            for (int nt = 0; nt < 4; ++nt) {
                u32 bfr[2];
                int row = n0b + nt * 8 + (lane & 7);
                int col = k0 + ((lane >> 3) & 1) * 8;
                ldsm2(bfr, s2u(&smh[OFF_WFT + row * 264 + col]));
                mma16816(c2[nt], afr, bfr);
            }
        }

#pragma unroll
        for (int nt = 0; nt < 4; ++nt) {
            int colg = n0b + nt * 8 + 2 * (lane & 3);
            int r0 = m0 + (lane >> 2), r1 = r0 + 8;
            int ng0 = node0 + r0, ng1 = node0 + r1;
            if (ng0 < N) {
                float d = sDinv[r0];
                *(__half2*)&g_Fph[ng0 * 64 + colg] =
                    __floats2half2_rn(c2[nt][0] * d, c2[nt][1] * d);
            }
            if (ng1 < N) {
                float d = sDinv[r1];
                *(__half2*)&g_Fph[ng1 * 64 + colg] =
                    __floats2half2_rn(c2[nt][2] * d, c2[nt][3] * d);
            }
        }
    }
}

// ---------------- layer-2 aggregation + bias + softmax (uint4 gather) -------
__global__ void k_agg_softmax(const float* __restrict__ bf, float* __restrict__ out, int N) {
    int tid = threadIdx.x;
    int glane = tid & 7;                 // 8 lanes per node, 8 logits each
    int n = blockIdx.x * 32 + (tid >> 3);
    if (n >= N) return;
    const uint4* feat = (const uint4*)g_Fph;
    float4 a0 = {0.f, 0.f, 0.f, 0.f};
    float4 a1 = {0.f, 0.f, 0.f, 0.f};
    {
        uint4 sv = feat[n * 8 + glane];  // self-loop term
        hadd4u(a0, sv.x, sv.y); hadd4u(a1, sv.z, sv.w);
    }
    int beg = g_off[n], end = g_off[n + 1];
    int j = beg;
    for (; j + 4 <= end; j += 4) {
        int u[4];
#pragma unroll
        for (int t = 0; t < 4; ++t) u[t] = g_csr[j + t];
        uint4 v4[4];
#pragma unroll
        for (int t = 0; t < 4; ++t) v4[t] = feat[u[t] * 8 + glane];
#pragma unroll
        for (int t = 0; t < 4; ++t) {
            hadd4u(a0, v4[t].x, v4[t].y);
            hadd4u(a1, v4[t].z, v4[t].w);
        }
    }
    for (; j < end; ++j) {
        uint4 vv = feat[g_csr[j] * 8 + glane];
        hadd4u(a0, vv.x, vv.y); hadd4u(a1, vv.z, vv.w);
    }
    float s = g_dinv[n];
    float4 b0 = ((const float4*)bf)[glane * 2];
    float4 b1 = ((const float4*)bf)[glane * 2 + 1];
    float4 z0 = {a0.x * s + b0.x, a0.y * s + b0.y, a0.z * s + b0.z, a0.w * s + b0.w};
    float4 z1 = {a1.x * s + b1.x, a1.y * s + b1.y, a1.z * s + b1.z, a1.w * s + b1.w};

    // softmax over 64 logits spread across 8 lanes (8 each)
    float m = fmaxf(fmaxf(fmaxf(z0.x, z0.y), fmaxf(z0.z, z0.w)),
                    fmaxf(fmaxf(z1.x, z1.y), fmaxf(z1.z, z1.w)));
#pragma unroll
    for (int o = 4; o > 0; o >>= 1)
        m = fmaxf(m, __shfl_xor_sync(0xffffffffu, m, o, 8));
    z0.x = __expf(z0.x - m); z0.y = __expf(z0.y - m);
    z0.z = __expf(z0.z - m); z0.w = __expf(z0.w - m);
    z1.x = __expf(z1.x - m); z1.y = __expf(z1.y - m);
    z1.z = __expf(z1.z - m); z1.w = __expf(z1.w - m);
    float sum = z0.x + z0.y + z0.z + z0.w + z1.x + z1.y + z1.z + z1.w;
#pragma unroll
    for (int o = 4; o > 0; o >>= 1)
        sum += __shfl_xor_sync(0xffffffffu, sum, o, 8);
    float inv = 1.0f / sum;
    z0.x *= inv; z0.y *= inv; z0.z *= inv; z0.w *= inv;
    z1.x *= inv; z1.y *= inv; z1.z *= inv; z1.w *= inv;
    ((float4*)out)[n * 16 + glane * 2]     = z0;
    ((float4*)out)[n * 16 + glane * 2 + 1] = z1;
}

// ---------------- launch ----------------------------------------------------
extern "C" void kernel_launch(void* const* d_in, const int* in_sizes, int n_in,
                              void* d_out, int out_size) {
    const float* X  = (const float*)d_in[0];
    const void*  ei = d_in[1];            // int32 or int64 — detected on device
    const float* Wn = (const float*)d_in[3];
    const float* bn = (const float*)d_in[4];
    const float* Ws = (const float*)d_in[5];
    const float* bs = (const float*)d_in[6];
    const float* Wf = (const float*)d_in[7];
    const float* bf = (const float*)d_in[8];
    float* out = (float*)d_out;

    int N = in_sizes[0] / 64;
    int E = in_sizes[1] / 2;
    int NB = (N + 1023) / 1024;
    int NB64 = (N + 63) / 64;
    int FB = (E + 2047) / 2048;           // fill blocks (512 thr x 4 edges)
    int PB = (N * 16 + 2047) / 2048;      // prep blocks (512 thr, ~4 quads each)

    cudaFuncSetAttribute(k_aggmlp, cudaFuncAttributeMaxDynamicSharedMemorySize,
                         MLP_SMEM_BYTES);

    k_init<<<128, 1024>>>((const unsigned int*)ei, E, N, Wn, Ws, Wf);
    k_hist<<<(E + 511) / 512, 512>>>(ei, E, N);
    k_scan<<<NB, 1024>>>(N, E);
    k_fillprep<<<FB + PB, 512>>>(ei, E, N, X, FB);
    k_aggmlp<<<NB64, 256, MLP_SMEM_BYTES>>>(bn, bs, N);
    k_agg_softmax<<<(N + 31) / 32, 256>>>(bf, out, N);
}

// round 14
// speedup vs baseline: 1.0912x; 1.0162x over previous
#include <cuda_runtime.h>
#include <cuda_fp16.h>
#include <cuda_bf16.h>

// Problem constants
#define MAXN 100000
#define MAXE 1600000

typedef unsigned long long ull;
typedef unsigned int u32;

// ---------------- scratch (device globals — no runtime allocation) ----------
__device__ int    g_is64;            // 1 if ei_feat is int64, 0 if int32
__device__ int    g_cnt[MAXN];
__device__ float  g_dinv[MAXN];
__device__ int    g_off[MAXN + 1];
__device__ int    g_cur[MAXN];
__device__ int    g_csr[MAXE];
__device__ int    g_bsum[256];       // decoupled scan: block_sum+1 (0 = not ready)
__device__ __half g_Xh[MAXN * 64];   // fp16(dinv[n] * X[n])        (gather src 1)
__device__ __half g_Fph[MAXN * 64];  // fp16(dinv[n] * (H @ Wf)[n]) (gather src 2)
// pre-transposed fp16 weights, padded rows for conflict-free ldmatrix
__device__ __half g_WTa[256 * 40];   // [n(256)][k(32)+8pad]  (Wn rows 0-127, Ws 128-255)
__device__ __half g_WfT[64 * 264];   // [n(64)][k(256)+8pad]

// ---------------- helpers ---------------------------------------------------
__device__ __forceinline__ int clampN(int v, int N) {
    v = v < 0 ? 0 : v;
    return v >= N ? N - 1 : v;
}

__device__ __forceinline__ int edge_at(const void* ei, int idx) {
    return g_is64 ? ((const int*)ei)[2 * idx] : ((const int*)ei)[idx];
}

__device__ __forceinline__ float elu1(float v) {
    return v > 0.f ? v : (__expf(v) - 1.0f);
}

__device__ __forceinline__ void hadd4u(float4& a, u32 lo, u32 hi) {
    float2 f0 = __half22float2(*reinterpret_cast<__half2*>(&lo));
    float2 f1 = __half22float2(*reinterpret_cast<__half2*>(&hi));
    a.x += f0.x; a.y += f0.y; a.z += f1.x; a.w += f1.y;
}

__device__ __forceinline__ uint2 pack4h(float a, float b, float c, float d) {
    union { __half2 h[2]; uint2 u; } cv;
    cv.h[0] = __floats2half2_rn(a, b);
    cv.h[1] = __floats2half2_rn(c, d);
    return cv.u;
}

__device__ __forceinline__ u32 s2u(const void* p) {
    return (u32)__cvta_generic_to_shared(p);
}
__device__ __forceinline__ void ldsm4(u32* r, u32 a) {
    asm volatile("ldmatrix.sync.aligned.m8n8.x4.shared.b16 {%0,%1,%2,%3}, [%4];"
        : "=r"(r[0]), "=r"(r[1]), "=r"(r[2]), "=r"(r[3]) : "r"(a));
}
__device__ __forceinline__ void ldsm2(u32* r, u32 a) {
    asm volatile("ldmatrix.sync.aligned.m8n8.x2.shared.b16 {%0,%1}, [%2];"
        : "=r"(r[0]), "=r"(r[1]) : "r"(a));
}
__device__ __forceinline__ void mma16816(float* c, const u32* a, const u32* b) {
    asm volatile("mma.sync.aligned.m16n8k16.row.col.f32.f16.f16.f32 "
        "{%0,%1,%2,%3}, {%4,%5,%6,%7}, {%8,%9}, {%0,%1,%2,%3};"
        : "+f"(c[0]), "+f"(c[1]), "+f"(c[2]), "+f"(c[3])
        : "r"(a[0]), "r"(a[1]), "r"(a[2]), "r"(a[3]), "r"(b[0]), "r"(b[1]));
}

// ---------------- k_init: dtype detect + zero cnt/bsum + weight fp16 --------
__global__ void k_init(const unsigned int* __restrict__ w, int E, int N,
                       const float* __restrict__ Wn, const float* __restrict__ Ws,
                       const float* __restrict__ Wf) {
    if (blockIdx.x == 0) {
        if (threadIdx.x == 0) g_is64 = 1;
        __syncthreads();
        int npairs = E < 1024 ? E : 1024;
        if ((int)threadIdx.x < npairs) {
            if (w[2 * threadIdx.x + 1] != 0u) atomicExch(&g_is64, 0);
        }
    }
    if (blockIdx.x == 1 && threadIdx.x < 256) g_bsum[threadIdx.x] = 0;

    int stride = gridDim.x * blockDim.x;
    int gtid = blockIdx.x * blockDim.x + threadIdx.x;
    for (int i = gtid; i < N; i += stride) g_cnt[i] = 0;
    for (int idx = gtid; idx < 4096; idx += stride) {
        int k = idx >> 7, n = idx & 127;           // Wn/Ws are [32][128]
        g_WTa[n * 40 + k]         = __float2half_rn(Wn[idx]);
        g_WTa[(n + 128) * 40 + k] = __float2half_rn(Ws[idx]);
    }
    for (int idx = gtid; idx < 16384; idx += stride) {
        int k = idx >> 6, n = idx & 63;            // Wf is [256][64]
        g_WfT[n * 264 + k] = __float2half_rn(Wf[idx]);
    }
}

// ---------------- CSR build -------------------------------------------------
// hist discards the atomic result -> ptxas emits REDG (fire-and-forget).
__global__ void k_hist(const void* __restrict__ ei, int E, int N) {
    int e = blockIdx.x * blockDim.x + threadIdx.x;
    if (e < E) {
        int dst = clampN(edge_at(ei, E + e), N);
        atomicAdd(&g_cnt[dst], 1);
    }
}

// Single-kernel scan: warp-shuffle block scan + decoupled aggregate lookback.
// All <=98 blocks are co-resident on 148 SMs (wave 1), so polling is safe.
__global__ void k_scan(int N, int E) {
    __shared__ int wsum[32];
    __shared__ int sPrefix;
    int tid = threadIdx.x, bid = blockIdx.x;
    int lane = tid & 31, wid = tid >> 5;
    int i = bid * 1024 + tid;
    int v = (i < N) ? g_cnt[i] : 0;

    // block-wide inclusive scan (shuffle)
    int incl = v;
#pragma unroll
    for (int o = 1; o < 32; o <<= 1) {
        int t = __shfl_up_sync(0xffffffffu, incl, o);
        if (lane >= o) incl += t;
    }
    if (lane == 31) wsum[wid] = incl;
    __syncthreads();
    if (wid == 0) {
        int wv = wsum[lane];
#pragma unroll
        for (int o = 1; o < 32; o <<= 1) {
            int t = __shfl_up_sync(0xffffffffu, wv, o);
            if (lane >= o) wv += t;
        }
        wsum[lane] = wv;                       // inclusive warp sums
    }
    __syncthreads();
    int incl_total = incl + (wid ? wsum[wid - 1] : 0);
    int block_sum = wsum[31];

    // publish our aggregate (value+1 so 0 == not-ready; single word => atomic)
    if (tid == 0) {
        atomicExch(&g_bsum[bid], block_sum + 1);
        sPrefix = 0;
    }
    __syncthreads();

    // lookback: poll all predecessors in parallel
    for (int b = tid; b < bid; b += 1024) {
        int vb;
        do { vb = atomicAdd(&g_bsum[b], 0); } while (vb == 0);
        atomicAdd_block(&sPrefix, vb - 1);
    }
    __syncthreads();
    int prefix = sPrefix;

    if (i < N) {
        int excl = prefix + incl_total - v;
        g_off[i] = excl;
        g_cur[i] = excl;
        g_dinv[i] = rsqrtf((float)(v + 1));
    }
    if (bid == 0 && tid == 0) g_off[N] = E;
}

// ---------------- fused fill + prep (block-specialized) ----------------------
// Blocks [0, FB): CSR fill, 8 edges/thread (8 independent atomics in flight).
// Blocks [FB, grid): g_Xh = fp16(dinv * X).
__global__ void k_fillprep(const void* __restrict__ ei, int E, int N,
                           const float* __restrict__ X, int FB) {
    if ((int)blockIdx.x < FB) {
        int e0 = blockIdx.x * 4096 + threadIdx.x;
        int dst[8], src[8];
        bool valid[8];
#pragma unroll
        for (int k = 0; k < 8; ++k) {
            int e = e0 + k * 512;
            valid[k] = e < E;
            if (valid[k]) {
                dst[k] = clampN(edge_at(ei, E + e), N);
                src[k] = clampN(edge_at(ei, e), N);
            }
        }
        int pos[8];
#pragma unroll
        for (int k = 0; k < 8; ++k)
            if (valid[k]) pos[k] = atomicAdd(&g_cur[dst[k]], 1);
#pragma unroll
        for (int k = 0; k < 8; ++k)
            if (valid[k] && pos[k] < MAXE) g_csr[pos[k]] = src[k];
    } else {
        int total = N * 16;                      // float4 quads
        int nthr = (gridDim.x - FB) * 512;
        for (int idx = (blockIdx.x - FB) * 512 + threadIdx.x; idx < total; idx += nthr) {
            int n = idx >> 4;
            float s = g_dinv[n];
            float4 v = ((const float4*)X)[idx];
            ((uint2*)g_Xh)[idx] = pack4h(v.x * s, v.y * s, v.z * s, v.w * s);
        }
    }
}

// ---------------- fused agg + HMMA MLP --------------------------------------
// Layouts (halves): sXh [64][72], sWTa [256][40], sH [64][264], sWfT [64][264]
#define OFF_XH   0
#define OFF_WTA  4608
#define OFF_H    14848
#define OFF_WFT  31744
#define HALVES_TOTAL 48640
#define MLP_SMEM_BYTES (HALVES_TOTAL * 2 + 256 * 4 + 64 * 4)

__global__ __launch_bounds__(256)
void k_aggmlp(const float* __restrict__ bn, const float* __restrict__ bs, int N) {
    extern __shared__ __half smh[];
    float* sBias = (float*)(smh + HALVES_TOTAL);
    float* sDinv = sBias + 256;

    int tid = threadIdx.x;
    int node0 = blockIdx.x * 64;
    int w = tid >> 5, lane = tid & 31;

    // ---- stage weights + bias + dinv ----
    {
        const uint4* s1 = (const uint4*)g_WTa;
        uint4* d1 = (uint4*)(smh + OFF_WTA);
        for (int i = tid; i < 1280; i += 256) d1[i] = s1[i];
        const uint4* s2 = (const uint4*)g_WfT;
        uint4* d2 = (uint4*)(smh + OFF_WFT);
        for (int i = tid; i < 2112; i += 256) d2[i] = s2[i];
        sBias[tid] = (tid < 128) ? bn[tid] : bs[tid - 128];
        if (tid < 64) {
            int n = node0 + tid;
            sDinv[tid] = (n < N) ? g_dinv[n] : 0.f;
        }
    }

    // ---- Phase 0: gather (uint4, 8 lanes/node, chunk-8 + idx prefetch) ----
    {
        int glane = tid & 7;             // 8 lanes per node, 8 halves each
        int nsub = tid >> 3;             // 32 nodes per pass, 2 passes
        const uint4* feat = (const uint4*)g_Xh;   // row = 8 uint4
#pragma unroll
        for (int pass = 0; pass < 2; ++pass) {
            int row = pass * 32 + nsub;
            int n = node0 + row;
            float4 a0 = {0.f, 0.f, 0.f, 0.f};
            float4 a1 = {0.f, 0.f, 0.f, 0.f};
            if (n < N) {
                uint4 sv = feat[n * 8 + glane];    // self-loop term
                hadd4u(a0, sv.x, sv.y); hadd4u(a1, sv.z, sv.w);
                int beg = g_off[n], end = g_off[n + 1];
                int j = beg;
                int u[8];
                bool have = (j + 8 <= end);
                if (have) {
#pragma unroll
                    for (int t = 0; t < 8; ++t) u[t] = g_csr[j + t];
                }
                while (have) {
                    uint4 v4[8];
#pragma unroll
                    for (int t = 0; t < 8; ++t) v4[t] = feat[u[t] * 8 + glane];
                    j += 8;
                    have = (j + 8 <= end);
                    if (have) {                     // prefetch next indices
#pragma unroll
                        for (int t = 0; t < 8; ++t) u[t] = g_csr[j + t];
                    }
#pragma unroll
                    for (int t = 0; t < 8; ++t) {
                        hadd4u(a0, v4[t].x, v4[t].y);
                        hadd4u(a1, v4[t].z, v4[t].w);
                    }
                }
                for (; j < end; ++j) {
                    uint4 vv = feat[g_csr[j] * 8 + glane];
                    hadd4u(a0, vv.x, vv.y); hadd4u(a1, vv.z, vv.w);
                }
                float dn = g_dinv[n];
                a0.x *= dn; a0.y *= dn; a0.z *= dn; a0.w *= dn;
                a1.x *= dn; a1.y *= dn; a1.z *= dn; a1.w *= dn;
            }
            uint2 p0 = pack4h(a0.x, a0.y, a0.z, a0.w);
            uint2 p1 = pack4h(a1.x, a1.y, a1.z, a1.w);
            *(uint4*)&smh[OFF_XH + row * 72 + glane * 8] =
                make_uint4(p0.x, p0.y, p1.x, p1.y);
        }
    }
    __syncthreads();

    // ---- Phase A: H[64][256] = elu(Xt @ blockdiag(Wn,Ws) + b), warp = 32 cols
    {
        int hsel = w >> 2;              // warps 0-3: cols 0-127 (nuc), 4-7: surf
        int n0w = w * 32;               // global col base
        float c[4][4][4];
#pragma unroll
        for (int mt = 0; mt < 4; ++mt)
#pragma unroll
            for (int nt = 0; nt < 4; ++nt)
#pragma unroll
                for (int i = 0; i < 4; ++i) c[mt][nt][i] = 0.f;

        u32 bfr[4][2][2];
#pragma unroll
        for (int nt = 0; nt < 4; ++nt)
#pragma unroll
            for (int ks = 0; ks < 2; ++ks) {
                int row = n0w + nt * 8 + (lane & 7);
                int col = ks * 16 + ((lane >> 3) & 1) * 8;
                ldsm2(bfr[nt][ks], s2u(&smh[OFF_WTA + row * 40 + col]));
            }

#pragma unroll
        for (int mt = 0; mt < 4; ++mt) {
            u32 afr[2][4];
#pragma unroll
            for (int ks = 0; ks < 2; ++ks) {
                int row = mt * 16 + (lane & 15);
                int col = hsel * 32 + ks * 16 + (lane >> 4) * 8;
                ldsm4(afr[ks], s2u(&smh[OFF_XH + row * 72 + col]));
            }
#pragma unroll
            for (int nt = 0; nt < 4; ++nt) {
                mma16816(c[mt][nt], afr[0], bfr[nt][0]);
                mma16816(c[mt][nt], afr[1], bfr[nt][1]);
            }
        }

        // epilogue: bias + elu -> sH fp16
#pragma unroll
        for (int mt = 0; mt < 4; ++mt)
#pragma unroll
            for (int nt = 0; nt < 4; ++nt) {
                int colg = n0w + nt * 8 + 2 * (lane & 3);
                float b0 = sBias[colg], b1 = sBias[colg + 1];
                int r0 = mt * 16 + (lane >> 2);
                *(__half2*)&smh[OFF_H + r0 * 264 + colg] =
                    __floats2half2_rn(elu1(c[mt][nt][0] + b0), elu1(c[mt][nt][1] + b1));
                *(__half2*)&smh[OFF_H + (r0 + 8) * 264 + colg] =
                    __floats2half2_rn(elu1(c[mt][nt][2] + b0), elu1(c[mt][nt][3] + b1));
            }
    }
    __syncthreads();

    // ---- Phase B: Fp[64][64] = dinv * (H @ Wf), warp tile 16x32, K=256 ----
    {
        int m0 = (w & 3) * 16, n0b = (w >> 2) * 32;
        float c2[4][4];
#pragma unroll
        for (int nt = 0; nt < 4; ++nt)
#pragma unroll
            for (int i = 0; i < 4; ++i) c2[nt][i] = 0.f;

        for (int ks = 0; ks < 16; ++ks) {
            int k0 = ks * 16;
            u32 afr[4];
            {
                int row = m0 + (lane & 15);
                int col = k0 + (lane >> 4) * 8;
                ldsm4(afr, s2u(&smh[OFF_H + row * 264 + col]));
            }
#pragma unroll
            for (int nt = 0; nt < 4; ++nt) {
                u32 bfr[2];
                int row = n0b + nt * 8 + (lane & 7);
                int col = k0 + ((lane >> 3) & 1) * 8;
                ldsm2(bfr, s2u(&smh[OFF_WFT + row * 264 + col]));
                mma16816(c2[nt], afr, bfr);
            }
        }

#pragma unroll
        for (int nt = 0; nt < 4; ++nt) {
            int colg = n0b + nt * 8 + 2 * (lane & 3);
            int r0 = m0 + (lane >> 2), r1 = r0 + 8;
            int ng0 = node0 + r0, ng1 = node0 + r1;
            if (ng0 < N) {
                float d = sDinv[r0];
                *(__half2*)&g_Fph[ng0 * 64 + colg] =
                    __floats2half2_rn(c2[nt][0] * d, c2[nt][1] * d);
            }
            if (ng1 < N) {
                float d = sDinv[r1];
                *(__half2*)&g_Fph[ng1 * 64 + colg] =
                    __floats2half2_rn(c2[nt][2] * d, c2[nt][3] * d);
            }
        }
    }
}

// ---------------- layer-2 agg + bias + softmax (chunk-8 + idx prefetch) -----
__global__ void k_agg_softmax(const float* __restrict__ bf, float* __restrict__ out, int N) {
    int tid = threadIdx.x;
    int glane = tid & 7;                 // 8 lanes per node, 8 logits each
    int n = blockIdx.x * 32 + (tid >> 3);
    if (n >= N) return;
    const uint4* feat = (const uint4*)g_Fph;
    float4 a0 = {0.f, 0.f, 0.f, 0.f};
    float4 a1 = {0.f, 0.f, 0.f, 0.f};
    {
        uint4 sv = feat[n * 8 + glane];  // self-loop term
        hadd4u(a0, sv.x, sv.y); hadd4u(a1, sv.z, sv.w);
    }
    int beg = g_off[n], end = g_off[n + 1];
    int j = beg;
    int u[8];
    bool have = (j + 8 <= end);
    if (have) {
#pragma unroll
        for (int t = 0; t < 8; ++t) u[t] = g_csr[j + t];
    }
    while (have) {
        uint4 v4[8];
#pragma unroll
        for (int t = 0; t < 8; ++t) v4[t] = feat[u[t] * 8 + glane];
        j += 8;
        have = (j + 8 <= end);
        if (have) {
#pragma unroll
            for (int t = 0; t < 8; ++t) u[t] = g_csr[j + t];
        }
#pragma unroll
        for (int t = 0; t < 8; ++t) {
            hadd4u(a0, v4[t].x, v4[t].y);
            hadd4u(a1, v4[t].z, v4[t].w);
        }
    }
    for (; j < end; ++j) {
        uint4 vv = feat[g_csr[j] * 8 + glane];
        hadd4u(a0, vv.x, vv.y); hadd4u(a1, vv.z, vv.w);
    }
    float s = g_dinv[n];
    float4 b0 = ((const float4*)bf)[glane * 2];
    float4 b1 = ((const float4*)bf)[glane * 2 + 1];
    float4 z0 = {a0.x * s + b0.x, a0.y * s + b0.y, a0.z * s + b0.z, a0.w * s + b0.w};
    float4 z1 = {a1.x * s + b1.x, a1.y * s + b1.y, a1.z * s + b1.z, a1.w * s + b1.w};

    // softmax over 64 logits spread across 8 lanes (8 each)
    float m = fmaxf(fmaxf(fmaxf(z0.x, z0.y), fmaxf(z0.z, z0.w)),
                    fmaxf(fmaxf(z1.x, z1.y), fmaxf(z1.z, z1.w)));
#pragma unroll
    for (int o = 4; o > 0; o >>= 1)
        m = fmaxf(m, __shfl_xor_sync(0xffffffffu, m, o, 8));
    z0.x = __expf(z0.x - m); z0.y = __expf(z0.y - m);
    z0.z = __expf(z0.z - m); z0.w = __expf(z0.w - m);
    z1.x = __expf(z1.x - m); z1.y = __expf(z1.y - m);
    z1.z = __expf(z1.z - m); z1.w = __expf(z1.w - m);
    float sum = z0.x + z0.y + z0.z + z0.w + z1.x + z1.y + z1.z + z1.w;
#pragma unroll
    for (int o = 4; o > 0; o >>= 1)
        sum += __shfl_xor_sync(0xffffffffu, sum, o, 8);
    float inv = 1.0f / sum;
    z0.x *= inv; z0.y *= inv; z0.z *= inv; z0.w *= inv;
    z1.x *= inv; z1.y *= inv; z1.z *= inv; z1.w *= inv;
    ((float4*)out)[n * 16 + glane * 2]     = z0;
    ((float4*)out)[n * 16 + glane * 2 + 1] = z1;
}

// ---------------- launch ----------------------------------------------------
extern "C" void kernel_launch(void* const* d_in, const int* in_sizes, int n_in,
                              void* d_out, int out_size) {
    const float* X  = (const float*)d_in[0];
    const void*  ei = d_in[1];            // int32 or int64 — detected on device
    const float* Wn = (const float*)d_in[3];
    const float* bn = (const float*)d_in[4];
    const float* Ws = (const float*)d_in[5];
    const float* bs = (const float*)d_in[6];
    const float* Wf = (const float*)d_in[7];
    const float* bf = (const float*)d_in[8];
    float* out = (float*)d_out;

    int N = in_sizes[0] / 64;
    int E = in_sizes[1] / 2;
    int NB = (N + 1023) / 1024;
    int NB64 = (N + 63) / 64;
    int FB = (E + 4095) / 4096;           // fill blocks (512 thr x 8 edges)
    int PB = (N * 16 + 2047) / 2048;      // prep blocks (512 thr, ~4 quads each)

    cudaFuncSetAttribute(k_aggmlp, cudaFuncAttributeMaxDynamicSharedMemorySize,
                         MLP_SMEM_BYTES);

    k_init<<<128, 1024>>>((const unsigned int*)ei, E, N, Wn, Ws, Wf);
    k_hist<<<(E + 511) / 512, 512>>>(ei, E, N);
    k_scan<<<NB, 1024>>>(N, E);
    k_fillprep<<<FB + PB, 512>>>(ei, E, N, X, FB);
    k_aggmlp<<<NB64, 256, MLP_SMEM_BYTES>>>(bn, bs, N);
    k_agg_softmax<<<(N + 31) / 32, 256>>>(bf, out, N);
}

// round 15
// speedup vs baseline: 1.3625x; 1.2487x over previous
#include <cuda_runtime.h>
#include <cuda_fp16.h>
#include <cuda_bf16.h>

// Problem constants
#define MAXN 100000
#define MAXE 1600000

typedef unsigned long long ull;
typedef unsigned int u32;

// ---------------- scratch (device globals — no runtime allocation) ----------
__device__ int    g_is64;            // 1 if ei_feat is int64, 0 if int32
__device__ int    g_cnt[MAXN];
__device__ float  g_dinv[MAXN];
__device__ int    g_off[MAXN + 1];
__device__ int    g_cur[MAXN];
__device__ int    g_csr[MAXE];
__device__ int    g_bsum[256];       // decoupled scan: block_sum+1 (0 = not ready)
__device__ __half g_Xh[MAXN * 64];   // fp16(dinv[n] * X[n])        (gather src 1)
__device__ __half g_Fph[MAXN * 64];  // fp16(dinv[n] * (H @ Wf)[n]) (gather src 2)
// precomputed mma B-fragment words (per tile, per lane): {b0, b1}
// FA: phase A weights, 64 tiles = (hsel 2)x(coltile 16)x(ks 2), 32 lanes
// FB: phase B weights, 128 tiles = (ntile 8)x(ks 16), 32 lanes
__device__ uint2  g_FA2[64 * 32];
__device__ uint2  g_FB2[128 * 32];

// ---------------- helpers ---------------------------------------------------
__device__ __forceinline__ int clampN(int v, int N) {
    v = v < 0 ? 0 : v;
    return v >= N ? N - 1 : v;
}

__device__ __forceinline__ int edge_at(const void* ei, int idx) {
    return g_is64 ? ((const int*)ei)[2 * idx] : ((const int*)ei)[idx];
}

__device__ __forceinline__ float elu1(float v) {
    return v > 0.f ? v : (__expf(v) - 1.0f);
}

__device__ __forceinline__ void hadd4u(float4& a, u32 lo, u32 hi) {
    float2 f0 = __half22float2(*reinterpret_cast<__half2*>(&lo));
    float2 f1 = __half22float2(*reinterpret_cast<__half2*>(&hi));
    a.x += f0.x; a.y += f0.y; a.z += f1.x; a.w += f1.y;
}

__device__ __forceinline__ uint2 pack4h(float a, float b, float c, float d) {
    union { __half2 h[2]; uint2 u; } cv;
    cv.h[0] = __floats2half2_rn(a, b);
    cv.h[1] = __floats2half2_rn(c, d);
    return cv.u;
}

__device__ __forceinline__ u32 s2u(const void* p) {
    return (u32)__cvta_generic_to_shared(p);
}
__device__ __forceinline__ void ldsm4(u32* r, u32 a) {
    asm volatile("ldmatrix.sync.aligned.m8n8.x4.shared.b16 {%0,%1,%2,%3}, [%4];"
        : "=r"(r[0]), "=r"(r[1]), "=r"(r[2]), "=r"(r[3]) : "r"(a));
}
__device__ __forceinline__ void mma16816(float* c, const u32* a, const u32* b) {
    asm volatile("mma.sync.aligned.m16n8k16.row.col.f32.f16.f16.f32 "
        "{%0,%1,%2,%3}, {%4,%5,%6,%7}, {%8,%9}, {%0,%1,%2,%3};"
        : "+f"(c[0]), "+f"(c[1]), "+f"(c[2]), "+f"(c[3])
        : "r"(a[0]), "r"(a[1]), "r"(a[2]), "r"(a[3]), "r"(b[0]), "r"(b[1]));
}

// ---------------- k_init: dtype detect + zero + weight fragment prep --------
// Fragment content for mma.m16n8k16.row.col B operand (verified against the
// previous ldmatrix path): lane t of a (8n x 16k) tile holds
//   b0 = half2(W[k0+2*(t%4)][n0+t/4],   W[k0+2*(t%4)+1][n0+t/4])
//   b1 = same with k0+8.
__global__ void k_init(const unsigned int* __restrict__ w, int E, int N,
                       const float* __restrict__ Wn, const float* __restrict__ Ws,
                       const float* __restrict__ Wf) {
    if (blockIdx.x == 0) {
        if (threadIdx.x == 0) g_is64 = 1;
        __syncthreads();
        int npairs = E < 1024 ? E : 1024;
        if ((int)threadIdx.x < npairs) {
            if (w[2 * threadIdx.x + 1] != 0u) atomicExch(&g_is64, 0);
        }
    }
    if (blockIdx.x == 1 && threadIdx.x < 256) g_bsum[threadIdx.x] = 0;

    int stride = gridDim.x * blockDim.x;
    int gtid = blockIdx.x * blockDim.x + threadIdx.x;
    for (int i = gtid; i < N; i += stride) g_cnt[i] = 0;

    // FA: Wn/Ws are [32][128] row-major (k-major)
    for (int idx = gtid; idx < 64 * 32; idx += stride) {
        int tile = idx >> 5, lane = idx & 31;
        int hsel = tile >> 5;            // 0 = Wn, 1 = Ws
        int ct = (tile >> 1) & 15;       // col tile over 128
        int ks = tile & 1;               // k tile (16 each, K=32)
        int n = ct * 8 + (lane >> 2);
        int k0 = ks * 16 + 2 * (lane & 3);
        const float* Wsrc = hsel ? Ws : Wn;
        __half2 b0 = __floats2half2_rn(Wsrc[k0 * 128 + n], Wsrc[(k0 + 1) * 128 + n]);
        __half2 b1 = __floats2half2_rn(Wsrc[(k0 + 8) * 128 + n], Wsrc[(k0 + 9) * 128 + n]);
        uint2 r;
        r.x = *reinterpret_cast<u32*>(&b0);
        r.y = *reinterpret_cast<u32*>(&b1);
        g_FA2[tile * 32 + lane] = r;
    }
    // FB: Wf is [256][64] row-major (k-major)
    for (int idx = gtid; idx < 128 * 32; idx += stride) {
        int tile = idx >> 5, lane = idx & 31;
        int ntile = tile >> 4;           // col tile over 64
        int ks = tile & 15;              // k tile over 256
        int n = ntile * 8 + (lane >> 2);
        int k0 = ks * 16 + 2 * (lane & 3);
        __half2 b0 = __floats2half2_rn(Wf[k0 * 64 + n], Wf[(k0 + 1) * 64 + n]);
        __half2 b1 = __floats2half2_rn(Wf[(k0 + 8) * 64 + n], Wf[(k0 + 9) * 64 + n]);
        uint2 r;
        r.x = *reinterpret_cast<u32*>(&b0);
        r.y = *reinterpret_cast<u32*>(&b1);
        g_FB2[tile * 32 + lane] = r;
    }
}

// ---------------- CSR build -------------------------------------------------
// hist discards the atomic result -> ptxas emits REDG (fire-and-forget).
__global__ void k_hist(const void* __restrict__ ei, int E, int N) {
    int e = blockIdx.x * blockDim.x + threadIdx.x;
    if (e < E) {
        int dst = clampN(edge_at(ei, E + e), N);
        atomicAdd(&g_cnt[dst], 1);
    }
}

// Single-kernel scan: warp-shuffle block scan + decoupled aggregate lookback.
__global__ void k_scan(int N, int E) {
    __shared__ int wsum[32];
    __shared__ int sPrefix;
    int tid = threadIdx.x, bid = blockIdx.x;
    int lane = tid & 31, wid = tid >> 5;
    int i = bid * 1024 + tid;
    int v = (i < N) ? g_cnt[i] : 0;

    int incl = v;
#pragma unroll
    for (int o = 1; o < 32; o <<= 1) {
        int t = __shfl_up_sync(0xffffffffu, incl, o);
        if (lane >= o) incl += t;
    }
    if (lane == 31) wsum[wid] = incl;
    __syncthreads();
    if (wid == 0) {
        int wv = wsum[lane];
#pragma unroll
        for (int o = 1; o < 32; o <<= 1) {
            int t = __shfl_up_sync(0xffffffffu, wv, o);
            if (lane >= o) wv += t;
        }
        wsum[lane] = wv;
    }
    __syncthreads();
    int incl_total = incl + (wid ? wsum[wid - 1] : 0);
    int block_sum = wsum[31];

    if (tid == 0) {
        atomicExch(&g_bsum[bid], block_sum + 1);
        sPrefix = 0;
    }
    __syncthreads();
    for (int b = tid; b < bid; b += 1024) {
        int vb;
        do { vb = atomicAdd(&g_bsum[b], 0); } while (vb == 0);
        atomicAdd_block(&sPrefix, vb - 1);
    }
    __syncthreads();
    int prefix = sPrefix;

    if (i < N) {
        int excl = prefix + incl_total - v;
        g_off[i] = excl;
        g_cur[i] = excl;
        g_dinv[i] = rsqrtf((float)(v + 1));
    }
    if (bid == 0 && tid == 0) g_off[N] = E;
}

// ---------------- fused fill + prep (block-specialized) ----------------------
// Blocks [0, FB): CSR fill, 4 edges/thread. Blocks [FB, grid): fp16 prep.
__global__ void k_fillprep(const void* __restrict__ ei, int E, int N,
                           const float* __restrict__ X, int FB) {
    if ((int)blockIdx.x < FB) {
        int e0 = blockIdx.x * 2048 + threadIdx.x;
        int dst[4], src[4];
        bool valid[4];
#pragma unroll
        for (int k = 0; k < 4; ++k) {
            int e = e0 + k * 512;
            valid[k] = e < E;
            if (valid[k]) {
                dst[k] = clampN(edge_at(ei, E + e), N);
                src[k] = clampN(edge_at(ei, e), N);
            }
        }
        int pos[4];
#pragma unroll
        for (int k = 0; k < 4; ++k)
            if (valid[k]) pos[k] = atomicAdd(&g_cur[dst[k]], 1);
#pragma unroll
        for (int k = 0; k < 4; ++k)
            if (valid[k] && pos[k] < MAXE) g_csr[pos[k]] = src[k];
    } else {
        int total = N * 16;                      // float4 quads
        int nthr = (gridDim.x - FB) * 512;
        for (int idx = (blockIdx.x - FB) * 512 + threadIdx.x; idx < total; idx += nthr) {
            int n = idx >> 4;
            float s = g_dinv[n];
            float4 v = ((const float4*)X)[idx];
            ((uint2*)g_Xh)[idx] = pack4h(v.x * s, v.y * s, v.z * s, v.w * s);
        }
    }
}

// ---------------- fused agg + HMMA MLP --------------------------------------
// smem: sXh [64][72] + sH [64][264] halves + bias/dinv -> ~44.3 KB => 3 blk/SM.
// Weights come as precomputed fragment words from global (L2-hot, coalesced).
#define OFF_XH   0
#define OFF_H    4608
#define HALVES_TOTAL (4608 + 16896)
#define MLP_SMEM_BYTES (HALVES_TOTAL * 2 + 256 * 4 + 64 * 4)

__global__ __launch_bounds__(256, 3)
void k_aggmlp(const float* __restrict__ bn, const float* __restrict__ bs, int N) {
    extern __shared__ __half smh[];
    float* sBias = (float*)(smh + HALVES_TOTAL);
    float* sDinv = sBias + 256;

    int tid = threadIdx.x;
    int node0 = blockIdx.x * 64;
    int w = tid >> 5, lane = tid & 31;

    // ---- stage bias + dinv ----
    sBias[tid] = (tid < 128) ? bn[tid] : bs[tid - 128];
    if (tid < 64) {
        int n = node0 + tid;
        sDinv[tid] = (n < N) ? g_dinv[n] : 0.f;
    }

    // ---- Phase 0: gather (uint4, 8 lanes/node, chunk-8 + idx prefetch) ----
    {
        int glane = tid & 7;             // 8 lanes per node, 8 halves each
        int nsub = tid >> 3;             // 32 nodes per pass, 2 passes
        const uint4* feat = (const uint4*)g_Xh;   // row = 8 uint4
#pragma unroll
        for (int pass = 0; pass < 2; ++pass) {
            int row = pass * 32 + nsub;
            int n = node0 + row;
            float4 a0 = {0.f, 0.f, 0.f, 0.f};
            float4 a1 = {0.f, 0.f, 0.f, 0.f};
            if (n < N) {
                uint4 sv = feat[n * 8 + glane];    // self-loop term
                hadd4u(a0, sv.x, sv.y); hadd4u(a1, sv.z, sv.w);
                int beg = g_off[n], end = g_off[n + 1];
                int j = beg;
                int u[8];
                bool have = (j + 8 <= end);
                if (have) {
#pragma unroll
                    for (int t = 0; t < 8; ++t) u[t] = g_csr[j + t];
                }
                while (have) {
                    uint4 v4[8];
#pragma unroll
                    for (int t = 0; t < 8; ++t) v4[t] = feat[u[t] * 8 + glane];
                    j += 8;
                    have = (j + 8 <= end);
                    if (have) {                     // prefetch next indices
#pragma unroll
                        for (int t = 0; t < 8; ++t) u[t] = g_csr[j + t];
                    }
#pragma unroll
                    for (int t = 0; t < 8; ++t) {
                        hadd4u(a0, v4[t].x, v4[t].y);
                        hadd4u(a1, v4[t].z, v4[t].w);
                    }
                }
                for (; j < end; ++j) {
                    uint4 vv = feat[g_csr[j] * 8 + glane];
                    hadd4u(a0, vv.x, vv.y); hadd4u(a1, vv.z, vv.w);
                }
                float dn = g_dinv[n];
                a0.x *= dn; a0.y *= dn; a0.z *= dn; a0.w *= dn;
                a1.x *= dn; a1.y *= dn; a1.z *= dn; a1.w *= dn;
            }
            uint2 p0 = pack4h(a0.x, a0.y, a0.z, a0.w);
            uint2 p1 = pack4h(a1.x, a1.y, a1.z, a1.w);
            *(uint4*)&smh[OFF_XH + row * 72 + glane * 8] =
                make_uint4(p0.x, p0.y, p1.x, p1.y);
        }
    }
    __syncthreads();

    // ---- Phase A: H[64][256] = elu(Xt @ blockdiag(Wn,Ws) + b), warp = 32 cols
    {
        int hsel = w >> 2;              // warps 0-3: cols 0-127 (nuc), 4-7: surf
        int n0w = w * 32;               // global col base
        float c[4][4][4];
#pragma unroll
        for (int mt = 0; mt < 4; ++mt)
#pragma unroll
            for (int nt = 0; nt < 4; ++nt)
#pragma unroll
                for (int i = 0; i < 4; ++i) c[mt][nt][i] = 0.f;

        // fragment words from global (L2-hot; one uint2 per (nt, ks) per lane)
        uint2 bfr[4][2];
#pragma unroll
        for (int nt = 0; nt < 4; ++nt)
#pragma unroll
            for (int ks = 0; ks < 2; ++ks)
                bfr[nt][ks] =
                    g_FA2[(((hsel * 16) + (w & 3) * 4 + nt) * 2 + ks) * 32 + lane];

#pragma unroll
        for (int mt = 0; mt < 4; ++mt) {
            u32 afr[2][4];
#pragma unroll
            for (int ks = 0; ks < 2; ++ks) {
                int row = mt * 16 + (lane & 15);
                int col = hsel * 32 + ks * 16 + (lane >> 4) * 8;
                ldsm4(afr[ks], s2u(&smh[OFF_XH + row * 72 + col]));
            }
#pragma unroll
            for (int nt = 0; nt < 4; ++nt) {
                mma16816(c[mt][nt], afr[0], (const u32*)&bfr[nt][0]);
                mma16816(c[mt][nt], afr[1], (const u32*)&bfr[nt][1]);
            }
        }

        // epilogue: bias + elu -> sH fp16
#pragma unroll
        for (int mt = 0; mt < 4; ++mt)
#pragma unroll
            for (int nt = 0; nt < 4; ++nt) {
                int colg = n0w + nt * 8 + 2 * (lane & 3);
                float b0 = sBias[colg], b1 = sBias[colg + 1];
                int r0 = mt * 16 + (lane >> 2);
                *(__half2*)&smh[OFF_H + r0 * 264 + colg] =
                    __floats2half2_rn(elu1(c[mt][nt][0] + b0), elu1(c[mt][nt][1] + b1));
                *(__half2*)&smh[OFF_H + (r0 + 8) * 264 + colg] =
                    __floats2half2_rn(elu1(c[mt][nt][2] + b0), elu1(c[mt][nt][3] + b1));
            }
    }
    __syncthreads();

    // ---- Phase B: Fp[64][64] = dinv * (H @ Wf), warp tile 16x32, K=256 ----
    {
        int m0 = (w & 3) * 16, n0b = (w >> 2) * 32;
        int ntile0 = n0b >> 3;
        float c2[4][4];
#pragma unroll
        for (int nt = 0; nt < 4; ++nt)
#pragma unroll
            for (int i = 0; i < 4; ++i) c2[nt][i] = 0.f;

        for (int ks = 0; ks < 16; ++ks) {
            int k0 = ks * 16;
            u32 afr[4];
            {
                int row = m0 + (lane & 15);
                int col = k0 + (lane >> 4) * 8;
                ldsm4(afr, s2u(&smh[OFF_H + row * 264 + col]));
            }
#pragma unroll
            for (int nt = 0; nt < 4; ++nt) {
                uint2 bfr = g_FB2[((ntile0 + nt) * 16 + ks) * 32 + lane];
                mma16816(c2[nt], afr, (const u32*)&bfr);
            }
        }

#pragma unroll
        for (int nt = 0; nt < 4; ++nt) {
            int colg = n0b + nt * 8 + 2 * (lane & 3);
            int r0 = m0 + (lane >> 2), r1 = r0 + 8;
            int ng0 = node0 + r0, ng1 = node0 + r1;
            if (ng0 < N) {
                float d = sDinv[r0];
                *(__half2*)&g_Fph[ng0 * 64 + colg] =
                    __floats2half2_rn(c2[nt][0] * d, c2[nt][1] * d);
            }
            if (ng1 < N) {
                float d = sDinv[r1];
                *(__half2*)&g_Fph[ng1 * 64 + colg] =
                    __floats2half2_rn(c2[nt][2] * d, c2[nt][3] * d);
            }
        }
    }
}

// ---------------- layer-2 agg + bias + softmax (chunk-8 + idx prefetch) -----
__global__ void k_agg_softmax(const float* __restrict__ bf, float* __restrict__ out, int N) {
    int tid = threadIdx.x;
    int glane = tid & 7;                 // 8 lanes per node, 8 logits each
    int n = blockIdx.x * 32 + (tid >> 3);
    if (n >= N) return;
    const uint4* feat = (const uint4*)g_Fph;
    float4 a0 = {0.f, 0.f, 0.f, 0.f};
    float4 a1 = {0.f, 0.f, 0.f, 0.f};
    {
        uint4 sv = feat[n * 8 + glane];  // self-loop term
        hadd4u(a0, sv.x, sv.y); hadd4u(a1, sv.z, sv.w);
    }
    int beg = g_off[n], end = g_off[n + 1];
    int j = beg;
    int u[8];
    bool have = (j + 8 <= end);
    if (have) {
#pragma unroll
        for (int t = 0; t < 8; ++t) u[t] = g_csr[j + t];
    }
    while (have) {
        uint4 v4[8];
#pragma unroll
        for (int t = 0; t < 8; ++t) v4[t] = feat[u[t] * 8 + glane];
        j += 8;
        have = (j + 8 <= end);
        if (have) {
#pragma unroll
            for (int t = 0; t < 8; ++t) u[t] = g_csr[j + t];
        }
#pragma unroll
        for (int t = 0; t < 8; ++t) {
            hadd4u(a0, v4[t].x, v4[t].y);
            hadd4u(a1, v4[t].z, v4[t].w);
        }
    }
    for (; j < end; ++j) {
        uint4 vv = feat[g_csr[j] * 8 + glane];
        hadd4u(a0, vv.x, vv.y); hadd4u(a1, vv.z, vv.w);
    }
    float s = g_dinv[n];
    float4 b0 = ((const float4*)bf)[glane * 2];
    float4 b1 = ((const float4*)bf)[glane * 2 + 1];
    float4 z0 = {a0.x * s + b0.x, a0.y * s + b0.y, a0.z * s + b0.z, a0.w * s + b0.w};
    float4 z1 = {a1.x * s + b1.x, a1.y * s + b1.y, a1.z * s + b1.z, a1.w * s + b1.w};

    float m = fmaxf(fmaxf(fmaxf(z0.x, z0.y), fmaxf(z0.z, z0.w)),
                    fmaxf(fmaxf(z1.x, z1.y), fmaxf(z1.z, z1.w)));
#pragma unroll
    for (int o = 4; o > 0; o >>= 1)
        m = fmaxf(m, __shfl_xor_sync(0xffffffffu, m, o, 8));
    z0.x = __expf(z0.x - m); z0.y = __expf(z0.y - m);
    z0.z = __expf(z0.z - m); z0.w = __expf(z0.w - m);
    z1.x = __expf(z1.x - m); z1.y = __expf(z1.y - m);
    z1.z = __expf(z1.z - m); z1.w = __expf(z1.w - m);
    float sum = z0.x + z0.y + z0.z + z0.w + z1.x + z1.y + z1.z + z1.w;
#pragma unroll
    for (int o = 4; o > 0; o >>= 1)
        sum += __shfl_xor_sync(0xffffffffu, sum, o, 8);
    float inv = 1.0f / sum;
    z0.x *= inv; z0.y *= inv; z0.z *= inv; z0.w *= inv;
    z1.x *= inv; z1.y *= inv; z1.z *= inv; z1.w *= inv;
    ((float4*)out)[n * 16 + glane * 2]     = z0;
    ((float4*)out)[n * 16 + glane * 2 + 1] = z1;
}

// ---------------- launch ----------------------------------------------------
extern "C" void kernel_launch(void* const* d_in, const int* in_sizes, int n_in,
                              void* d_out, int out_size) {
    const float* X  = (const float*)d_in[0];
    const void*  ei = d_in[1];            // int32 or int64 — detected on device
    const float* Wn = (const float*)d_in[3];
    const float* bn = (const float*)d_in[4];
    const float* Ws = (const float*)d_in[5];
    const float* bs = (const float*)d_in[6];
    const float* Wf = (const float*)d_in[7];
    const float* bf = (const float*)d_in[8];
    float* out = (float*)d_out;

    int N = in_sizes[0] / 64;
    int E = in_sizes[1] / 2;
    int NB = (N + 1023) / 1024;
    int NB64 = (N + 63) / 64;
    int FB = (E + 2047) / 2048;           // fill blocks (512 thr x 4 edges)
    int PB = (N * 16 + 2047) / 2048;      // prep blocks

    cudaFuncSetAttribute(k_aggmlp, cudaFuncAttributeMaxDynamicSharedMemorySize,
                         MLP_SMEM_BYTES);

    k_init<<<128, 1024>>>((const unsigned int*)ei, E, N, Wn, Ws, Wf);
    k_hist<<<(E + 511) / 512, 512>>>(ei, E, N);
    k_scan<<<NB, 1024>>>(N, E);
    k_fillprep<<<FB + PB, 512>>>(ei, E, N, X, FB);
    k_aggmlp<<<NB64, 256, MLP_SMEM_BYTES>>>(bn, bs, N);
    k_agg_softmax<<<(N + 31) / 32, 256>>>(bf, out, N);
}